// round 12
// baseline (speedup 1.0000x reference)
#include <cuda_runtime.h>
#include <cstdint>

#define HDIM   512
#define TLEN   2048
#define NBATCH 16
#define CLSZ   8
#define NCLUSTER (NBATCH / 2)       // 8 clusters, 2 batches each

typedef unsigned long long u64;
typedef unsigned int u32;

// ---------------- PTX helpers ----------------
__device__ __forceinline__ u32 smem_u32(const void* p) {
    u32 a;
    asm("{ .reg .u64 t; cvta.to.shared.u64 t, %1; cvt.u32.u64 %0, t; }" : "=r"(a) : "l"(p));
    return a;
}
__device__ __forceinline__ void fma2(u64& d, u64 a, u64 b) {
    asm("fma.rn.f32x2 %0, %1, %2, %0;" : "+l"(d) : "l"(a), "l"(b));
}
__device__ __forceinline__ u64 pk2(float lo, float hi) {
    u64 r; asm("mov.b64 %0, {%1, %2};" : "=l"(r) : "f"(lo), "f"(hi)); return r;
}
__device__ __forceinline__ float lo32(u64 v) { return __uint_as_float((u32)(v & 0xffffffffull)); }
__device__ __forceinline__ float hi32(u64 v) { return __uint_as_float((u32)(v >> 32)); }
__device__ __forceinline__ u32 mapa32(u32 a, u32 r) {
    u32 d; asm("mapa.shared::cluster.u32 %0, %1, %2;" : "=r"(d) : "r"(a), "r"(r)); return d;
}
__device__ __forceinline__ void st_async32(u32 ra, u32 v, u32 rb) {
    asm volatile("st.async.shared::cluster.mbarrier::complete_tx::bytes.b32 [%0], %1, [%2];"
                 :: "r"(ra), "r"(v), "r"(rb) : "memory");
}
__device__ __forceinline__ void mbar_init(u32 m, u32 cnt) {
    asm volatile("mbarrier.init.shared.b64 [%0], %1;" :: "r"(m), "r"(cnt) : "memory");
}
__device__ __forceinline__ void mbar_expect_tx(u32 m, u32 bytes) {
    asm volatile("mbarrier.arrive.expect_tx.shared.b64 _, [%0], %1;" :: "r"(m), "r"(bytes) : "memory");
}
__device__ __forceinline__ void mbar_wait_parity(u32 m, u32 parity) {
    asm volatile(
        "{\n\t.reg .pred P;\nLW_%=:\n\t"
        "mbarrier.try_wait.parity.acquire.cluster.shared::cta.b64 P, [%0], %1, 0x989680;\n\t"
        "@!P bra LW_%=;\n\t}"
        :: "r"(m), "r"(parity) : "memory");
}
__device__ __forceinline__ void cluster_sync_() {
    asm volatile("barrier.cluster.arrive.aligned;" ::: "memory");
    asm volatile("barrier.cluster.wait.aligned;" ::: "memory");
}
__device__ __forceinline__ void bar_arrive(int id) {
    asm volatile("bar.arrive %0, 512;" :: "r"(id) : "memory");
}
__device__ __forceinline__ void bar_sync_named(int id) {
    asm volatile("bar.sync %0, 512;" :: "r"(id) : "memory");
}
// tanh(x) = sign(x)*(1-e)/(1+e), e = exp2(-2x*log2e), ~1e-7 abs err
__device__ __forceinline__ float fast_tanh(float x) {
    float ax = fabsf(x);
    float e;
    asm("ex2.approx.ftz.f32 %0, %1;" : "=f"(e) : "f"(ax * -2.885390082f));
    float r;
    asm("rcp.approx.ftz.f32 %0, %1;" : "=f"(r) : "f"(1.0f + e));
    return copysignf((1.0f - e) * r, x);
}

// ---------------- Phase 1: pre = X @ W_xh + b  (M=32768, N=512, K=512) ----------------
// Known-good: 128x64 tile, BK=16, 256 threads, 8x4 microtile, plain fp32.
__global__ __launch_bounds__(256) void pre_gemm(
    const float* __restrict__ X, const float* __restrict__ W,
    const float* __restrict__ bias, float* __restrict__ P)
{
    __shared__ __align__(16) float As[16][130];
    __shared__ __align__(16) float Bs[16][64];
    const int tid = threadIdx.x;
    const int tx  = tid & 15;
    const int ty  = tid >> 4;
    const int m0  = blockIdx.x * 128;
    const int n0  = blockIdx.y * 64;
    const int arow = tid >> 1;
    const int ak   = (tid & 1) * 8;
    const int bk   = tid >> 4;
    const int bn   = (tid & 15) * 4;

    float acc[8][4];
    #pragma unroll
    for (int i = 0; i < 8; i++)
        #pragma unroll
        for (int j = 0; j < 4; j++) acc[i][j] = 0.0f;

    for (int kb = 0; kb < 32; kb++) {
        const int k0 = kb * 16;
        const float* Xp = X + (m0 + arow) * HDIM + k0 + ak;
        float4 a0 = *(const float4*)Xp;
        float4 a1 = *(const float4*)(Xp + 4);
        float4 bv = *(const float4*)(W + (k0 + bk) * HDIM + n0 + bn);
        As[ak+0][arow] = a0.x; As[ak+1][arow] = a0.y; As[ak+2][arow] = a0.z; As[ak+3][arow] = a0.w;
        As[ak+4][arow] = a1.x; As[ak+5][arow] = a1.y; As[ak+6][arow] = a1.z; As[ak+7][arow] = a1.w;
        *(float4*)&Bs[bk][bn] = bv;
        __syncthreads();
        #pragma unroll
        for (int k = 0; k < 16; k++) {
            float4 rb = *(const float4*)&Bs[k][tx * 4];
            float ra[8];
            #pragma unroll
            for (int i = 0; i < 4; i++) {
                float2 t2 = *(const float2*)&As[k][ty * 8 + 2 * i];
                ra[2*i] = t2.x; ra[2*i+1] = t2.y;
            }
            #pragma unroll
            for (int i = 0; i < 8; i++) {
                acc[i][0] += ra[i] * rb.x;
                acc[i][1] += ra[i] * rb.y;
                acc[i][2] += ra[i] * rb.z;
                acc[i][3] += ra[i] * rb.w;
            }
        }
        __syncthreads();
    }
    float4 bb = *(const float4*)(bias + n0 + tx * 4);
    #pragma unroll
    for (int i = 0; i < 8; i++) {
        float4 o;
        o.x = acc[i][0] + bb.x; o.y = acc[i][1] + bb.y;
        o.z = acc[i][2] + bb.z; o.w = acc[i][3] + bb.w;
        *(float4*)&P[(m0 + ty * 8 + i) * HDIM + n0 + tx * 4] = o;
    }
}

// ---------------- Phase 2: scan, 2 batches per cluster, split barriers ----------------
// Per-batch mbarrier pairs: waitA gates only on A-sends (transport hidden under
// previous step's B phase); waitB gates only on B-sends (transport hidden under
// this step's A phase). Warps 0-1 finish A, warps 2-3 finish B; producers only
// bar.arrive. Weights shared by both batches in registers.
__global__ __launch_bounds__(512, 1) __cluster_dims__(CLSZ, 1, 1)
void rnn_scan(const float* __restrict__ Whh, float* __restrict__ out)
{
    __shared__ __align__(16) float hA[2][HDIM];
    __shared__ __align__(16) float hB[2][HDIM];
    __shared__ __align__(16) float redA[16][64];
    __shared__ __align__(16) float redB[16][64];
    __shared__ __align__(16) u64 mbar[4];   // [0,1]=A phase0/1, [2,3]=B phase0/1

    const int tid  = threadIdx.x;
    const int wi   = tid >> 5;
    const int lane = tid & 31;
    const int rank = blockIdx.x & (CLSZ - 1);
    const int cl   = blockIdx.x / CLSZ;
    const int jg   = tid & 15;                   // 4-col group
    const int kc   = tid >> 4;                   // 16-k chunk (0..31)

    // W_hh[:, rank*64 + jg*4 .. +4) for k in [kc*16, +16), packed (k,k+1)
    u64 w[4][8];
    {
        const int j0 = rank * 64 + jg * 4;
        const int kb = kc * 16;
        #pragma unroll
        for (int p = 0; p < 8; p++) {
            float4 l4 = *(const float4*)(Whh + (kb + 2*p)     * HDIM + j0);
            float4 h4 = *(const float4*)(Whh + (kb + 2*p + 1) * HDIM + j0);
            w[0][p] = pk2(l4.x, h4.x);
            w[1][p] = pk2(l4.y, h4.y);
            w[2][p] = pk2(l4.z, h4.z);
            w[3][p] = pk2(l4.w, h4.w);
        }
    }

    hA[0][tid] = 0.0f; hA[1][tid] = 0.0f;
    hB[0][tid] = 0.0f; hB[1][tid] = 0.0f;
    const u32 hAa = smem_u32(&hA[0][0]);
    const u32 hBa = smem_u32(&hB[0][0]);
    const u32 mb0 = smem_u32(&mbar[0]);
    if (tid == 0) {
        mbar_init(mb0,      1);
        mbar_init(mb0 + 8,  1);
        mbar_init(mb0 + 16, 1);
        mbar_init(mb0 + 24, 1);
        asm volatile("fence.mbarrier_init.release.cluster;" ::: "memory");
    }
    __syncthreads();
    cluster_sync_();

    const long baseA = (long)(2 * cl)     * TLEN * HDIM + rank * 64;
    const long baseB = (long)(2 * cl + 1) * TLEN * HDIM + rank * 64;
    float preA = 0.0f, preB = 0.0f;
    if (tid < 64)       preA = out[baseA + tid];
    else if (tid < 128) preB = out[baseB + (tid - 64)];

    for (int t = 0; t < TLEN; ++t) {
        const int pb = t & 1;
        const int nb = pb ^ 1;
        const u32 par = (u32)(((t - 2 + pb) >> 1) & 1);
        if (t > 0) mbar_wait_parity(mb0 + (u32)pb * 8u, par);   // A barrier

        // ---- matvec A (all warps) ----
        {
            const ulonglong2* hp = (const ulonglong2*)&hA[pb][kc * 16];
            u64 a0 = 0ull, a1 = 0ull, a2 = 0ull, a3 = 0ull;
            #pragma unroll
            for (int p = 0; p < 4; p++) {
                ulonglong2 hv = hp[p];
                fma2(a0, hv.x, w[0][2*p]);   fma2(a1, hv.x, w[1][2*p]);
                fma2(a2, hv.x, w[2][2*p]);   fma2(a3, hv.x, w[3][2*p]);
                fma2(a0, hv.y, w[0][2*p+1]); fma2(a1, hv.y, w[1][2*p+1]);
                fma2(a2, hv.y, w[2][2*p+1]); fma2(a3, hv.y, w[3][2*p+1]);
            }
            float s0 = lo32(a0) + hi32(a0);
            float s1 = lo32(a1) + hi32(a1);
            float s2 = lo32(a2) + hi32(a2);
            float s3 = lo32(a3) + hi32(a3);
            s0 += __shfl_down_sync(0xffffffffu, s0, 16);
            s1 += __shfl_down_sync(0xffffffffu, s1, 16);
            s2 += __shfl_down_sync(0xffffffffu, s2, 16);
            s3 += __shfl_down_sync(0xffffffffu, s3, 16);
            if (lane < 16) {
                float4 v; v.x = s0; v.y = s1; v.z = s2; v.w = s3;
                *(float4*)&redA[wi][jg * 4] = v;
            }
        }
        if (wi < 2) {
            bar_sync_named(1);
            // ---- finish A (warps 0-1, col = tid) ----
            float p0 = redA[0][tid],  p1 = redA[1][tid],  p2 = redA[2][tid],  p3 = redA[3][tid];
            float p4 = redA[4][tid],  p5 = redA[5][tid],  p6 = redA[6][tid],  p7 = redA[7][tid];
            float p8 = redA[8][tid],  p9 = redA[9][tid],  pa = redA[10][tid], pc = redA[11][tid];
            float pd = redA[12][tid], pe = redA[13][tid], pf = redA[14][tid], pg = redA[15][tid];
            float sum = (((p0+p1)+(p2+p3)) + ((p4+p5)+(p6+p7)))
                      + (((p8+p9)+(pa+pc)) + ((pd+pe)+(pf+pg)));
            const float hv = fast_tanh(sum + preA);
            if (t + 1 < TLEN) {
                const u32 val  = __float_as_uint(hv);
                const u32 dloc = hAa + (u32)nb * (HDIM * 4) + (u32)(rank * 64 + tid) * 4;
                const u32 bloc = mb0 + (u32)nb * 8u;
                if (tid == 0) mbar_expect_tx(bloc, CLSZ * 64 * 4);   // 2048 B
                #pragma unroll
                for (int r = 0; r < CLSZ; r++)
                    st_async32(mapa32(dloc, (u32)r), val, mapa32(bloc, (u32)r));
                out[baseA + (long)t * HDIM + tid] = hv;
                preA = out[baseA + (long)(t + 1) * HDIM + tid];
            } else {
                out[baseA + (long)t * HDIM + tid] = hv;
            }
        } else {
            bar_arrive(1);
        }

        // B barrier: sends happened mid-previous-step, transport hidden under A phase
        if (t > 0) mbar_wait_parity(mb0 + 16u + (u32)pb * 8u, par);

        // ---- matvec B (all warps) ----
        {
            const ulonglong2* hp = (const ulonglong2*)&hB[pb][kc * 16];
            u64 a0 = 0ull, a1 = 0ull, a2 = 0ull, a3 = 0ull;
            #pragma unroll
            for (int p = 0; p < 4; p++) {
                ulonglong2 hv = hp[p];
                fma2(a0, hv.x, w[0][2*p]);   fma2(a1, hv.x, w[1][2*p]);
                fma2(a2, hv.x, w[2][2*p]);   fma2(a3, hv.x, w[3][2*p]);
                fma2(a0, hv.y, w[0][2*p+1]); fma2(a1, hv.y, w[1][2*p+1]);
                fma2(a2, hv.y, w[2][2*p+1]); fma2(a3, hv.y, w[3][2*p+1]);
            }
            float s0 = lo32(a0) + hi32(a0);
            float s1 = lo32(a1) + hi32(a1);
            float s2 = lo32(a2) + hi32(a2);
            float s3 = lo32(a3) + hi32(a3);
            s0 += __shfl_down_sync(0xffffffffu, s0, 16);
            s1 += __shfl_down_sync(0xffffffffu, s1, 16);
            s2 += __shfl_down_sync(0xffffffffu, s2, 16);
            s3 += __shfl_down_sync(0xffffffffu, s3, 16);
            if (lane < 16) {
                float4 v; v.x = s0; v.y = s1; v.z = s2; v.w = s3;
                *(float4*)&redB[wi][jg * 4] = v;
            }
        }
        if (wi == 2 || wi == 3) {
            bar_sync_named(2);
            // ---- finish B (warps 2-3, col = tid - 64) ----
            const int c = tid - 64;
            float p0 = redB[0][c],  p1 = redB[1][c],  p2 = redB[2][c],  p3 = redB[3][c];
            float p4 = redB[4][c],  p5 = redB[5][c],  p6 = redB[6][c],  p7 = redB[7][c];
            float p8 = redB[8][c],  p9 = redB[9][c],  pa = redB[10][c], pc = redB[11][c];
            float pd = redB[12][c], pe = redB[13][c], pf = redB[14][c], pg = redB[15][c];
            float sum = (((p0+p1)+(p2+p3)) + ((p4+p5)+(p6+p7)))
                      + (((p8+p9)+(pa+pc)) + ((pd+pe)+(pf+pg)));
            const float hv = fast_tanh(sum + preB);
            if (t + 1 < TLEN) {
                const u32 val  = __float_as_uint(hv);
                const u32 dloc = hBa + (u32)nb * (HDIM * 4) + (u32)(rank * 64 + c) * 4;
                const u32 bloc = mb0 + 16u + (u32)nb * 8u;
                if (c == 0) mbar_expect_tx(bloc, CLSZ * 64 * 4);    // 2048 B
                #pragma unroll
                for (int r = 0; r < CLSZ; r++)
                    st_async32(mapa32(dloc, (u32)r), val, mapa32(bloc, (u32)r));
                out[baseB + (long)t * HDIM + c] = hv;
                preB = out[baseB + (long)(t + 1) * HDIM + c];
            } else {
                out[baseB + (long)t * HDIM + c] = hv;
            }
        } else {
            bar_arrive(2);
        }
    }
    cluster_sync_();
}

// ---------------- launch ----------------
extern "C" void kernel_launch(void* const* d_in, const int* in_sizes, int n_in,
                              void* d_out, int out_size) {
    (void)in_sizes; (void)n_in; (void)out_size;
    const float* x    = (const float*)d_in[0];
    const float* Wxh  = (const float*)d_in[1];
    const float* Whh  = (const float*)d_in[2];
    const float* bias = (const float*)d_in[3];
    float* out = (float*)d_out;   // d_in[4] = A: backward-only, unused

    dim3 g1(NBATCH * TLEN / 128, HDIM / 64);
    pre_gemm<<<g1, 256>>>(x, Wxh, bias, out);            // pre (+bias) into out
    rnn_scan<<<NCLUSTER * CLSZ, 512>>>(Whh, out);        // in-place scan, 2 batches/cluster
}

// round 13
// speedup vs baseline: 1.3202x; 1.3202x over previous
#include <cuda_runtime.h>
#include <cstdint>

#define HDIM   512
#define TLEN   2048
#define NBATCH 16
#define CLSZ   8
#define NCLUSTER (NBATCH / 2)       // 8 clusters, 2 batches each
#define NTHREADS 576                // 16 producer warps + 2 finisher warps
#define BARCNT   544                // 512 producers + 32 finisher threads

typedef unsigned long long u64;
typedef unsigned int u32;

// ---------------- PTX helpers ----------------
__device__ __forceinline__ u32 smem_u32(const void* p) {
    u32 a;
    asm("{ .reg .u64 t; cvta.to.shared.u64 t, %1; cvt.u32.u64 %0, t; }" : "=r"(a) : "l"(p));
    return a;
}
__device__ __forceinline__ void fma2(u64& d, u64 a, u64 b) {
    asm("fma.rn.f32x2 %0, %1, %2, %0;" : "+l"(d) : "l"(a), "l"(b));
}
__device__ __forceinline__ u64 pk2(float lo, float hi) {
    u64 r; asm("mov.b64 %0, {%1, %2};" : "=l"(r) : "f"(lo), "f"(hi)); return r;
}
__device__ __forceinline__ float lo32(u64 v) { return __uint_as_float((u32)(v & 0xffffffffull)); }
__device__ __forceinline__ float hi32(u64 v) { return __uint_as_float((u32)(v >> 32)); }
__device__ __forceinline__ u32 mapa32(u32 a, u32 r) {
    u32 d; asm("mapa.shared::cluster.u32 %0, %1, %2;" : "=r"(d) : "r"(a), "r"(r)); return d;
}
__device__ __forceinline__ void st_async64(u32 ra, u64 v, u32 rb) {
    asm volatile("st.async.shared::cluster.mbarrier::complete_tx::bytes.b64 [%0], %1, [%2];"
                 :: "r"(ra), "l"(v), "r"(rb) : "memory");
}
__device__ __forceinline__ void mbar_init(u32 m, u32 cnt) {
    asm volatile("mbarrier.init.shared.b64 [%0], %1;" :: "r"(m), "r"(cnt) : "memory");
}
__device__ __forceinline__ void mbar_expect_tx(u32 m, u32 bytes) {
    asm volatile("mbarrier.arrive.expect_tx.shared.b64 _, [%0], %1;" :: "r"(m), "r"(bytes) : "memory");
}
__device__ __forceinline__ void mbar_wait_parity(u32 m, u32 parity) {
    asm volatile(
        "{\n\t.reg .pred P;\nLW_%=:\n\t"
        "mbarrier.try_wait.parity.acquire.cluster.shared::cta.b64 P, [%0], %1, 0x989680;\n\t"
        "@!P bra LW_%=;\n\t}"
        :: "r"(m), "r"(parity) : "memory");
}
__device__ __forceinline__ void cluster_sync_() {
    asm volatile("barrier.cluster.arrive.aligned;" ::: "memory");
    asm volatile("barrier.cluster.wait.aligned;" ::: "memory");
}
__device__ __forceinline__ void bar_arrive(int id) {
    asm volatile("bar.arrive %0, %1;" :: "r"(id), "r"(BARCNT) : "memory");
}
__device__ __forceinline__ void bar_sync_named(int id) {
    asm volatile("bar.sync %0, %1;" :: "r"(id), "r"(BARCNT) : "memory");
}
// tanh(x) = sign(x)*(1-e)/(1+e), e = exp2(-2x*log2e), ~1e-7 abs err
__device__ __forceinline__ float fast_tanh(float x) {
    float ax = fabsf(x);
    float e;
    asm("ex2.approx.ftz.f32 %0, %1;" : "=f"(e) : "f"(ax * -2.885390082f));
    float r;
    asm("rcp.approx.ftz.f32 %0, %1;" : "=f"(r) : "f"(1.0f + e));
    return copysignf((1.0f - e) * r, x);
}

// ---------------- Phase 1: pre = X @ W_xh + b  (M=32768, N=512, K=512) ----------------
// Known-good: 128x64 tile, BK=16, 256 threads, 8x4 microtile, plain fp32.
__global__ __launch_bounds__(256) void pre_gemm(
    const float* __restrict__ X, const float* __restrict__ W,
    const float* __restrict__ bias, float* __restrict__ P)
{
    __shared__ __align__(16) float As[16][130];
    __shared__ __align__(16) float Bs[16][64];
    const int tid = threadIdx.x;
    const int tx  = tid & 15;
    const int ty  = tid >> 4;
    const int m0  = blockIdx.x * 128;
    const int n0  = blockIdx.y * 64;
    const int arow = tid >> 1;
    const int ak   = (tid & 1) * 8;
    const int bk   = tid >> 4;
    const int bn   = (tid & 15) * 4;

    float acc[8][4];
    #pragma unroll
    for (int i = 0; i < 8; i++)
        #pragma unroll
        for (int j = 0; j < 4; j++) acc[i][j] = 0.0f;

    for (int kb = 0; kb < 32; kb++) {
        const int k0 = kb * 16;
        const float* Xp = X + (m0 + arow) * HDIM + k0 + ak;
        float4 a0 = *(const float4*)Xp;
        float4 a1 = *(const float4*)(Xp + 4);
        float4 bv = *(const float4*)(W + (k0 + bk) * HDIM + n0 + bn);
        As[ak+0][arow] = a0.x; As[ak+1][arow] = a0.y; As[ak+2][arow] = a0.z; As[ak+3][arow] = a0.w;
        As[ak+4][arow] = a1.x; As[ak+5][arow] = a1.y; As[ak+6][arow] = a1.z; As[ak+7][arow] = a1.w;
        *(float4*)&Bs[bk][bn] = bv;
        __syncthreads();
        #pragma unroll
        for (int k = 0; k < 16; k++) {
            float4 rb = *(const float4*)&Bs[k][tx * 4];
            float ra[8];
            #pragma unroll
            for (int i = 0; i < 4; i++) {
                float2 t2 = *(const float2*)&As[k][ty * 8 + 2 * i];
                ra[2*i] = t2.x; ra[2*i+1] = t2.y;
            }
            #pragma unroll
            for (int i = 0; i < 8; i++) {
                acc[i][0] += ra[i] * rb.x;
                acc[i][1] += ra[i] * rb.y;
                acc[i][2] += ra[i] * rb.z;
                acc[i][3] += ra[i] * rb.w;
            }
        }
        __syncthreads();
    }
    float4 bb = *(const float4*)(bias + n0 + tx * 4);
    #pragma unroll
    for (int i = 0; i < 8; i++) {
        float4 o;
        o.x = acc[i][0] + bb.x; o.y = acc[i][1] + bb.y;
        o.z = acc[i][2] + bb.z; o.w = acc[i][3] + bb.w;
        *(float4*)&P[(m0 + ty * 8 + i) * HDIM + n0 + tx * 4] = o;
    }
}

// ---------------- Phase 2: scan — dedicated finisher warps ----------------
// 576 threads: warps 0-15 = producers (matvec only), warp 16 = batch-A finisher,
// warp 17 = batch-B finisher. Producers: waitA, mvA, arrive(1), waitB, mvB,
// arrive(2). Finishers: bar.sync, reduce 16 partials, tanh, packed b64 sends.
// Split per-batch mbarriers: sendB(t-1) lands mid-iteration, waitB(t) sits
// after mvA -> transport hidden on both chains.
__global__ __launch_bounds__(NTHREADS, 1) __cluster_dims__(CLSZ, 1, 1)
void rnn_scan(const float* __restrict__ Whh, float* __restrict__ out)
{
    __shared__ __align__(16) float hA[2][HDIM];
    __shared__ __align__(16) float hB[2][HDIM];
    __shared__ __align__(16) float redA[16][64];
    __shared__ __align__(16) float redB[16][64];
    __shared__ __align__(16) u64 mbar[4];   // [0,1]=A ph0/1, [2,3]=B ph0/1

    const int tid  = threadIdx.x;
    const int wi   = tid >> 5;
    const int lane = tid & 31;
    const int rank = blockIdx.x & (CLSZ - 1);
    const int cl   = blockIdx.x / CLSZ;

    // init shared state (all 576 threads)
    for (int i = tid; i < 2 * HDIM; i += NTHREADS) { hA[0][i & (HDIM-1)] = 0.0f; }
    if (tid < 2 * HDIM) { ((float*)hA)[tid] = 0.0f; ((float*)hB)[tid] = 0.0f; }
    const u32 hAa = smem_u32(&hA[0][0]);
    const u32 hBa = smem_u32(&hB[0][0]);
    const u32 mb0 = smem_u32(&mbar[0]);
    if (tid == 0) {
        mbar_init(mb0,      1);
        mbar_init(mb0 + 8,  1);
        mbar_init(mb0 + 16, 1);
        mbar_init(mb0 + 24, 1);
        asm volatile("fence.mbarrier_init.release.cluster;" ::: "memory");
    }
    __syncthreads();
    cluster_sync_();

    const long baseA = (long)(2 * cl)     * TLEN * HDIM + rank * 64;
    const long baseB = (long)(2 * cl + 1) * TLEN * HDIM + rank * 64;

    if (wi < 16) {
        // ================= producers =================
        const int jg = tid & 15;     // 4-col group
        const int kc = tid >> 4;     // 16-k chunk (0..31)
        u64 w[4][8];
        {
            const int j0 = rank * 64 + jg * 4;
            const int kb = kc * 16;
            #pragma unroll
            for (int p = 0; p < 8; p++) {
                float4 l4 = *(const float4*)(Whh + (kb + 2*p)     * HDIM + j0);
                float4 h4 = *(const float4*)(Whh + (kb + 2*p + 1) * HDIM + j0);
                w[0][p] = pk2(l4.x, h4.x);
                w[1][p] = pk2(l4.y, h4.y);
                w[2][p] = pk2(l4.z, h4.z);
                w[3][p] = pk2(l4.w, h4.w);
            }
        }
        for (int t = 0; t < TLEN; ++t) {
            const int pb = t & 1;
            const u32 par = (u32)(((t - 2 + pb) >> 1) & 1);

            if (t > 0) mbar_wait_parity(mb0 + (u32)pb * 8u, par);      // A ready
            {
                const ulonglong2* hp = (const ulonglong2*)&hA[pb][kc * 16];
                u64 a0 = 0ull, a1 = 0ull, a2 = 0ull, a3 = 0ull;
                #pragma unroll
                for (int p = 0; p < 4; p++) {
                    ulonglong2 hv = hp[p];
                    fma2(a0, hv.x, w[0][2*p]);   fma2(a1, hv.x, w[1][2*p]);
                    fma2(a2, hv.x, w[2][2*p]);   fma2(a3, hv.x, w[3][2*p]);
                    fma2(a0, hv.y, w[0][2*p+1]); fma2(a1, hv.y, w[1][2*p+1]);
                    fma2(a2, hv.y, w[2][2*p+1]); fma2(a3, hv.y, w[3][2*p+1]);
                }
                float s0 = lo32(a0) + hi32(a0);
                float s1 = lo32(a1) + hi32(a1);
                float s2 = lo32(a2) + hi32(a2);
                float s3 = lo32(a3) + hi32(a3);
                s0 += __shfl_down_sync(0xffffffffu, s0, 16);
                s1 += __shfl_down_sync(0xffffffffu, s1, 16);
                s2 += __shfl_down_sync(0xffffffffu, s2, 16);
                s3 += __shfl_down_sync(0xffffffffu, s3, 16);
                if (lane < 16) {
                    float4 v; v.x = s0; v.y = s1; v.z = s2; v.w = s3;
                    *(float4*)&redA[wi][jg * 4] = v;
                }
            }
            bar_arrive(1);

            if (t > 0) mbar_wait_parity(mb0 + 16u + (u32)pb * 8u, par); // B ready
            {
                const ulonglong2* hp = (const ulonglong2*)&hB[pb][kc * 16];
                u64 a0 = 0ull, a1 = 0ull, a2 = 0ull, a3 = 0ull;
                #pragma unroll
                for (int p = 0; p < 4; p++) {
                    ulonglong2 hv = hp[p];
                    fma2(a0, hv.x, w[0][2*p]);   fma2(a1, hv.x, w[1][2*p]);
                    fma2(a2, hv.x, w[2][2*p]);   fma2(a3, hv.x, w[3][2*p]);
                    fma2(a0, hv.y, w[0][2*p+1]); fma2(a1, hv.y, w[1][2*p+1]);
                    fma2(a2, hv.y, w[2][2*p+1]); fma2(a3, hv.y, w[3][2*p+1]);
                }
                float s0 = lo32(a0) + hi32(a0);
                float s1 = lo32(a1) + hi32(a1);
                float s2 = lo32(a2) + hi32(a2);
                float s3 = lo32(a3) + hi32(a3);
                s0 += __shfl_down_sync(0xffffffffu, s0, 16);
                s1 += __shfl_down_sync(0xffffffffu, s1, 16);
                s2 += __shfl_down_sync(0xffffffffu, s2, 16);
                s3 += __shfl_down_sync(0xffffffffu, s3, 16);
                if (lane < 16) {
                    float4 v; v.x = s0; v.y = s1; v.z = s2; v.w = s3;
                    *(float4*)&redB[wi][jg * 4] = v;
                }
            }
            bar_arrive(2);
        }
    } else {
        // ================= finishers =================
        const int isB   = (wi == 17);
        const long base = isB ? baseB : baseA;
        const u32 hXa   = isB ? hBa : hAa;
        const u32 mbX   = mb0 + (isB ? 16u : 0u);
        const int barid = isB ? 2 : 1;
        const float* red = isB ? &redB[0][0] : &redA[0][0];
        const int c0 = 2 * lane;            // two adjacent columns

        float2 pre2 = *(const float2*)&out[base + c0];
        for (int t = 0; t < TLEN; ++t) {
            const int nb = (t & 1) ^ 1;
            bar_sync_named(barid);          // red(t) complete
            float2 s[4];
            #pragma unroll
            for (int q = 0; q < 4; q++) {
                float2 v0 = *(const float2*)&red[(4*q + 0) * 64 + c0];
                float2 v1 = *(const float2*)&red[(4*q + 1) * 64 + c0];
                float2 v2 = *(const float2*)&red[(4*q + 2) * 64 + c0];
                float2 v3 = *(const float2*)&red[(4*q + 3) * 64 + c0];
                s[q].x = (v0.x + v1.x) + (v2.x + v3.x);
                s[q].y = (v0.y + v1.y) + (v2.y + v3.y);
            }
            const float sum0 = (s[0].x + s[1].x) + (s[2].x + s[3].x);
            const float sum1 = (s[0].y + s[1].y) + (s[2].y + s[3].y);
            const float h0 = fast_tanh(sum0 + pre2.x);
            const float h1 = fast_tanh(sum1 + pre2.y);
            if (t + 1 < TLEN) {
                const u32 bloc = mbX + (u32)nb * 8u;
                if (lane == 0) mbar_expect_tx(bloc, CLSZ * 64 * 4);   // 2048 B
                const u64 pv   = pk2(h0, h1);
                const u32 dloc = hXa + (u32)nb * (HDIM * 4) + (u32)(rank * 64 + c0) * 4;
                #pragma unroll
                for (int r = 0; r < CLSZ; r++)
                    st_async64(mapa32(dloc, (u32)r), pv, mapa32(bloc, (u32)r));
                float2 o; o.x = h0; o.y = h1;
                *(float2*)&out[base + (long)t * HDIM + c0] = o;
                pre2 = *(const float2*)&out[base + (long)(t + 1) * HDIM + c0];
            } else {
                float2 o; o.x = h0; o.y = h1;
                *(float2*)&out[base + (long)t * HDIM + c0] = o;
            }
        }
    }
    cluster_sync_();
}

// ---------------- launch ----------------
extern "C" void kernel_launch(void* const* d_in, const int* in_sizes, int n_in,
                              void* d_out, int out_size) {
    (void)in_sizes; (void)n_in; (void)out_size;
    const float* x    = (const float*)d_in[0];
    const float* Wxh  = (const float*)d_in[1];
    const float* Whh  = (const float*)d_in[2];
    const float* bias = (const float*)d_in[3];
    float* out = (float*)d_out;   // d_in[4] = A: backward-only, unused

    dim3 g1(NBATCH * TLEN / 128, HDIM / 64);
    pre_gemm<<<g1, 256>>>(x, Wxh, bias, out);            // pre (+bias) into out
    rnn_scan<<<NCLUSTER * CLSZ, NTHREADS>>>(Whh, out);   // in-place scan
}

// round 14
// speedup vs baseline: 1.4090x; 1.0673x over previous
#include <cuda_runtime.h>
#include <cstdint>

#define HDIM   512
#define TLEN   2048
#define NBATCH 16
#define CLSZ   8
#define NCLUSTER (NBATCH / 2)       // 8 clusters, 2 batches each
#define NTHREADS 640                // 16 producer warps + 4 finisher warps
#define BARCNT   576                // 512 producers + 64 finisher threads (per batch barrier)

typedef unsigned long long u64;
typedef unsigned int u32;

// ---------------- PTX helpers ----------------
__device__ __forceinline__ u32 smem_u32(const void* p) {
    u32 a;
    asm("{ .reg .u64 t; cvta.to.shared.u64 t, %1; cvt.u32.u64 %0, t; }" : "=r"(a) : "l"(p));
    return a;
}
__device__ __forceinline__ void fma2(u64& d, u64 a, u64 b) {
    asm("fma.rn.f32x2 %0, %1, %2, %0;" : "+l"(d) : "l"(a), "l"(b));
}
__device__ __forceinline__ u64 pk2(float lo, float hi) {
    u64 r; asm("mov.b64 %0, {%1, %2};" : "=l"(r) : "f"(lo), "f"(hi)); return r;
}
__device__ __forceinline__ float lo32(u64 v) { return __uint_as_float((u32)(v & 0xffffffffull)); }
__device__ __forceinline__ float hi32(u64 v) { return __uint_as_float((u32)(v >> 32)); }
__device__ __forceinline__ u32 mapa32(u32 a, u32 r) {
    u32 d; asm("mapa.shared::cluster.u32 %0, %1, %2;" : "=r"(d) : "r"(a), "r"(r)); return d;
}
__device__ __forceinline__ void st_async32(u32 ra, u32 v, u32 rb) {
    asm volatile("st.async.shared::cluster.mbarrier::complete_tx::bytes.b32 [%0], %1, [%2];"
                 :: "r"(ra), "r"(v), "r"(rb) : "memory");
}
__device__ __forceinline__ void mbar_init(u32 m, u32 cnt) {
    asm volatile("mbarrier.init.shared.b64 [%0], %1;" :: "r"(m), "r"(cnt) : "memory");
}
__device__ __forceinline__ void mbar_expect_tx(u32 m, u32 bytes) {
    asm volatile("mbarrier.arrive.expect_tx.shared.b64 _, [%0], %1;" :: "r"(m), "r"(bytes) : "memory");
}
__device__ __forceinline__ void mbar_wait_parity(u32 m, u32 parity) {
    asm volatile(
        "{\n\t.reg .pred P;\nLW_%=:\n\t"
        "mbarrier.try_wait.parity.acquire.cluster.shared::cta.b64 P, [%0], %1, 0x989680;\n\t"
        "@!P bra LW_%=;\n\t}"
        :: "r"(m), "r"(parity) : "memory");
}
__device__ __forceinline__ void cluster_sync_() {
    asm volatile("barrier.cluster.arrive.aligned;" ::: "memory");
    asm volatile("barrier.cluster.wait.aligned;" ::: "memory");
}
__device__ __forceinline__ void bar_arrive(int id) {
    asm volatile("bar.arrive %0, %1;" :: "r"(id), "r"(BARCNT) : "memory");
}
__device__ __forceinline__ void bar_sync_named(int id) {
    asm volatile("bar.sync %0, %1;" :: "r"(id), "r"(BARCNT) : "memory");
}
// tanh(x) = sign(x)*(1-e)/(1+e), e = exp2(-2x*log2e), ~1e-7 abs err
__device__ __forceinline__ float fast_tanh(float x) {
    float ax = fabsf(x);
    float e;
    asm("ex2.approx.ftz.f32 %0, %1;" : "=f"(e) : "f"(ax * -2.885390082f));
    float r;
    asm("rcp.approx.ftz.f32 %0, %1;" : "=f"(r) : "f"(1.0f + e));
    return copysignf((1.0f - e) * r, x);
}

// ---------------- Phase 1: pre = X @ W_xh + b  (M=32768, N=512, K=512) ----------------
// Known-good: 128x64 tile, BK=16, 256 threads, 8x4 microtile, plain fp32.
__global__ __launch_bounds__(256) void pre_gemm(
    const float* __restrict__ X, const float* __restrict__ W,
    const float* __restrict__ bias, float* __restrict__ P)
{
    __shared__ __align__(16) float As[16][130];
    __shared__ __align__(16) float Bs[16][64];
    const int tid = threadIdx.x;
    const int tx  = tid & 15;
    const int ty  = tid >> 4;
    const int m0  = blockIdx.x * 128;
    const int n0  = blockIdx.y * 64;
    const int arow = tid >> 1;
    const int ak   = (tid & 1) * 8;
    const int bk   = tid >> 4;
    const int bn   = (tid & 15) * 4;

    float acc[8][4];
    #pragma unroll
    for (int i = 0; i < 8; i++)
        #pragma unroll
        for (int j = 0; j < 4; j++) acc[i][j] = 0.0f;

    for (int kb = 0; kb < 32; kb++) {
        const int k0 = kb * 16;
        const float* Xp = X + (m0 + arow) * HDIM + k0 + ak;
        float4 a0 = *(const float4*)Xp;
        float4 a1 = *(const float4*)(Xp + 4);
        float4 bv = *(const float4*)(W + (k0 + bk) * HDIM + n0 + bn);
        As[ak+0][arow] = a0.x; As[ak+1][arow] = a0.y; As[ak+2][arow] = a0.z; As[ak+3][arow] = a0.w;
        As[ak+4][arow] = a1.x; As[ak+5][arow] = a1.y; As[ak+6][arow] = a1.z; As[ak+7][arow] = a1.w;
        *(float4*)&Bs[bk][bn] = bv;
        __syncthreads();
        #pragma unroll
        for (int k = 0; k < 16; k++) {
            float4 rb = *(const float4*)&Bs[k][tx * 4];
            float ra[8];
            #pragma unroll
            for (int i = 0; i < 4; i++) {
                float2 t2 = *(const float2*)&As[k][ty * 8 + 2 * i];
                ra[2*i] = t2.x; ra[2*i+1] = t2.y;
            }
            #pragma unroll
            for (int i = 0; i < 8; i++) {
                acc[i][0] += ra[i] * rb.x;
                acc[i][1] += ra[i] * rb.y;
                acc[i][2] += ra[i] * rb.z;
                acc[i][3] += ra[i] * rb.w;
            }
        }
        __syncthreads();
    }
    float4 bb = *(const float4*)(bias + n0 + tx * 4);
    #pragma unroll
    for (int i = 0; i < 8; i++) {
        float4 o;
        o.x = acc[i][0] + bb.x; o.y = acc[i][1] + bb.y;
        o.z = acc[i][2] + bb.z; o.w = acc[i][3] + bb.w;
        *(float4*)&P[(m0 + ty * 8 + i) * HDIM + n0 + tx * 4] = o;
    }
}

// ---------------- Phase 2: scan — 4 finisher warps (2 per batch) ----------------
// 640 threads: warps 0-15 producers (matvec only); warps 16-17 finish batch A,
// warps 18-19 finish batch B, ONE column per finisher lane. Shorter finisher
// chain (16 scalar loads + 15-add tree + 1 tanh + 8 b32 sends) shrinks the
// release path: last producer arrive -> bar release -> reduce/tanh/send ->
// DSMEM transport -> peer wait.
__global__ __launch_bounds__(NTHREADS, 1) __cluster_dims__(CLSZ, 1, 1)
void rnn_scan(const float* __restrict__ Whh, float* __restrict__ out)
{
    __shared__ __align__(16) float hA[2][HDIM];
    __shared__ __align__(16) float hB[2][HDIM];
    __shared__ __align__(16) float redA[16][64];
    __shared__ __align__(16) float redB[16][64];
    __shared__ __align__(16) u64 mbar[4];   // [0,1]=A ph0/1, [2,3]=B ph0/1

    const int tid  = threadIdx.x;
    const int wi   = tid >> 5;
    const int lane = tid & 31;
    const int rank = blockIdx.x & (CLSZ - 1);
    const int cl   = blockIdx.x / CLSZ;

    for (int i = tid; i < 2 * HDIM; i += NTHREADS) {
        ((float*)hA)[i] = 0.0f;
        ((float*)hB)[i] = 0.0f;
    }
    const u32 hAa = smem_u32(&hA[0][0]);
    const u32 hBa = smem_u32(&hB[0][0]);
    const u32 mb0 = smem_u32(&mbar[0]);
    if (tid == 0) {
        mbar_init(mb0,      1);
        mbar_init(mb0 + 8,  1);
        mbar_init(mb0 + 16, 1);
        mbar_init(mb0 + 24, 1);
        asm volatile("fence.mbarrier_init.release.cluster;" ::: "memory");
    }
    __syncthreads();
    cluster_sync_();

    const long baseA = (long)(2 * cl)     * TLEN * HDIM + rank * 64;
    const long baseB = (long)(2 * cl + 1) * TLEN * HDIM + rank * 64;

    if (wi < 16) {
        // ================= producers =================
        const int jg = tid & 15;     // 4-col group
        const int kc = tid >> 4;     // 16-k chunk (0..31)
        u64 w[4][8];
        {
            const int j0 = rank * 64 + jg * 4;
            const int kb = kc * 16;
            #pragma unroll
            for (int p = 0; p < 8; p++) {
                float4 l4 = *(const float4*)(Whh + (kb + 2*p)     * HDIM + j0);
                float4 h4 = *(const float4*)(Whh + (kb + 2*p + 1) * HDIM + j0);
                w[0][p] = pk2(l4.x, h4.x);
                w[1][p] = pk2(l4.y, h4.y);
                w[2][p] = pk2(l4.z, h4.z);
                w[3][p] = pk2(l4.w, h4.w);
            }
        }
        for (int t = 0; t < TLEN; ++t) {
            const int pb = t & 1;
            const u32 par = (u32)(((t - 2 + pb) >> 1) & 1);

            if (t > 0) mbar_wait_parity(mb0 + (u32)pb * 8u, par);      // A ready
            {
                const ulonglong2* hp = (const ulonglong2*)&hA[pb][kc * 16];
                u64 a0 = 0ull, a1 = 0ull, a2 = 0ull, a3 = 0ull;
                #pragma unroll
                for (int p = 0; p < 4; p++) {
                    ulonglong2 hv = hp[p];
                    fma2(a0, hv.x, w[0][2*p]);   fma2(a1, hv.x, w[1][2*p]);
                    fma2(a2, hv.x, w[2][2*p]);   fma2(a3, hv.x, w[3][2*p]);
                    fma2(a0, hv.y, w[0][2*p+1]); fma2(a1, hv.y, w[1][2*p+1]);
                    fma2(a2, hv.y, w[2][2*p+1]); fma2(a3, hv.y, w[3][2*p+1]);
                }
                float s0 = lo32(a0) + hi32(a0);
                float s1 = lo32(a1) + hi32(a1);
                float s2 = lo32(a2) + hi32(a2);
                float s3 = lo32(a3) + hi32(a3);
                s0 += __shfl_down_sync(0xffffffffu, s0, 16);
                s1 += __shfl_down_sync(0xffffffffu, s1, 16);
                s2 += __shfl_down_sync(0xffffffffu, s2, 16);
                s3 += __shfl_down_sync(0xffffffffu, s3, 16);
                if (lane < 16) {
                    float4 v; v.x = s0; v.y = s1; v.z = s2; v.w = s3;
                    *(float4*)&redA[wi][jg * 4] = v;
                }
            }
            bar_arrive(1);

            if (t > 0) mbar_wait_parity(mb0 + 16u + (u32)pb * 8u, par); // B ready
            {
                const ulonglong2* hp = (const ulonglong2*)&hB[pb][kc * 16];
                u64 a0 = 0ull, a1 = 0ull, a2 = 0ull, a3 = 0ull;
                #pragma unroll
                for (int p = 0; p < 4; p++) {
                    ulonglong2 hv = hp[p];
                    fma2(a0, hv.x, w[0][2*p]);   fma2(a1, hv.x, w[1][2*p]);
                    fma2(a2, hv.x, w[2][2*p]);   fma2(a3, hv.x, w[3][2*p]);
                    fma2(a0, hv.y, w[0][2*p+1]); fma2(a1, hv.y, w[1][2*p+1]);
                    fma2(a2, hv.y, w[2][2*p+1]); fma2(a3, hv.y, w[3][2*p+1]);
                }
                float s0 = lo32(a0) + hi32(a0);
                float s1 = lo32(a1) + hi32(a1);
                float s2 = lo32(a2) + hi32(a2);
                float s3 = lo32(a3) + hi32(a3);
                s0 += __shfl_down_sync(0xffffffffu, s0, 16);
                s1 += __shfl_down_sync(0xffffffffu, s1, 16);
                s2 += __shfl_down_sync(0xffffffffu, s2, 16);
                s3 += __shfl_down_sync(0xffffffffu, s3, 16);
                if (lane < 16) {
                    float4 v; v.x = s0; v.y = s1; v.z = s2; v.w = s3;
                    *(float4*)&redB[wi][jg * 4] = v;
                }
            }
            bar_arrive(2);
        }
    } else {
        // ================= finishers =================
        const int wf    = wi - 16;          // 0,1 = batch A; 2,3 = batch B
        const int isB   = wf >> 1;
        const long base = isB ? baseB : baseA;
        const u32 hXa   = isB ? hBa : hAa;
        const u32 mbX   = mb0 + (isB ? 16u : 0u);
        const int barid = isB ? 2 : 1;
        const float* red = isB ? &redB[0][0] : &redA[0][0];
        const int col   = (wf & 1) * 32 + lane;   // one column per lane
        const int doExpect = ((wf & 1) == 0) && (lane == 0);

        float pre = out[base + col];
        for (int t = 0; t < TLEN; ++t) {
            const int nb = (t & 1) ^ 1;
            bar_sync_named(barid);          // red(t) complete
            float p0 = red[ 0*64 + col], p1 = red[ 1*64 + col];
            float p2 = red[ 2*64 + col], p3 = red[ 3*64 + col];
            float p4 = red[ 4*64 + col], p5 = red[ 5*64 + col];
            float p6 = red[ 6*64 + col], p7 = red[ 7*64 + col];
            float p8 = red[ 8*64 + col], p9 = red[ 9*64 + col];
            float pa = red[10*64 + col], pc = red[11*64 + col];
            float pd = red[12*64 + col], pe = red[13*64 + col];
            float pf = red[14*64 + col], pg = red[15*64 + col];
            float sum = (((p0+p1)+(p2+p3)) + ((p4+p5)+(p6+p7)))
                      + (((p8+p9)+(pa+pc)) + ((pd+pe)+(pf+pg)));
            const float hv = fast_tanh(sum + pre);
            if (t + 1 < TLEN) {
                const u32 bloc = mbX + (u32)nb * 8u;
                if (doExpect) mbar_expect_tx(bloc, CLSZ * 64 * 4);   // 2048 B
                const u32 val  = __float_as_uint(hv);
                const u32 dloc = hXa + (u32)nb * (HDIM * 4) + (u32)(rank * 64 + col) * 4;
                #pragma unroll
                for (int r = 0; r < CLSZ; r++)
                    st_async32(mapa32(dloc, (u32)r), val, mapa32(bloc, (u32)r));
                out[base + (long)t * HDIM + col] = hv;
                pre = out[base + (long)(t + 1) * HDIM + col];
            } else {
                out[base + (long)t * HDIM + col] = hv;
            }
        }
    }
    cluster_sync_();
}

// ---------------- launch ----------------
extern "C" void kernel_launch(void* const* d_in, const int* in_sizes, int n_in,
                              void* d_out, int out_size) {
    (void)in_sizes; (void)n_in; (void)out_size;
    const float* x    = (const float*)d_in[0];
    const float* Wxh  = (const float*)d_in[1];
    const float* Whh  = (const float*)d_in[2];
    const float* bias = (const float*)d_in[3];
    float* out = (float*)d_out;   // d_in[4] = A: backward-only, unused

    dim3 g1(NBATCH * TLEN / 128, HDIM / 64);
    pre_gemm<<<g1, 256>>>(x, Wxh, bias, out);            // pre (+bias) into out
    rnn_scan<<<NCLUSTER * CLSZ, NTHREADS>>>(Whh, out);   // in-place scan
}